// round 4
// baseline (speedup 1.0000x reference)
#include <cuda_runtime.h>

// Soft decision tree path probabilities — barrier-free, smem-free.
// DEPTH=8, N_NODES=255, N_LEAVES=256, BATCH=512.
//
// 64 threads per row; thread u owns the depth-6 subtree over leaves 4u..4u+3.
// All 9 x-loads it needs are index-computable and issued together:
//   top path  d=0..5 : node = (2^d-1) + (u >> (6-d))   (one 128B line region)
//   depth-6          : 63 + u                          (warp-coalesced)
//   depth-7          : 127+2u, 128+2u                  (warp-coalesced)
// Prefix product before the depth-d factor IS node_d's path prob:
//   top nodes written by leftmost thread of each subtree (u low bits zero),
//   nodes 63+u / 127+2u / 128+2u written unconditionally by owner thread.
// Child 2i+1 takes factor x[i], child 2i+2 takes 1-x[i].
//
// Output: [ leaf_probs (512 x 256) ; node_probs (512 x 255) ] row-major.

#define ROWS_PER_BLOCK 4   // 64 threads/row * 4 rows = 256 threads/CTA

__global__ __launch_bounds__(256) void tree_path_kernel(
    const float* __restrict__ x,   // (BATCH, 255)
    float* __restrict__ out,
    int batch)
{
    const int tid = threadIdx.x;
    const int r = tid >> 6;            // row slot 0..3
    const int u = tid & 63;            // subtree index 0..63
    const int b = blockIdx.x * ROWS_PER_BLOCK + r;

    const float* __restrict__ xr = x + (size_t)b * 255;
    float* __restrict__ out_nodes = out + (size_t)batch * 256 + (size_t)b * 255;

    // ---- issue all loads up front (9 independent LDGs) ----
    float xt[6];
#pragma unroll
    for (int d = 0; d < 6; ++d) {
        const int node = ((1 << d) - 1) + (u >> (6 - d));
        xt[d] = __ldg(xr + node);
    }
    const float x6  = __ldg(xr + 63 + u);
    const float x7a = __ldg(xr + 127 + 2 * u);
    const float x7b = __ldg(xr + 128 + 2 * u);

    // ---- top path prefix product, emitting node probs ----
    float p = 1.0f;
#pragma unroll
    for (int d = 0; d < 6; ++d) {
        const int node = ((1 << d) - 1) + (u >> (6 - d));
        if ((u & ((1 << (6 - d)) - 1)) == 0) {
            out_nodes[node] = p;       // path prob of node at depth d
        }
        p *= ((u >> (5 - d)) & 1) ? (1.0f - xt[d]) : xt[d];
    }

    // ---- depth 6 node (63+u), owned exclusively by this thread ----
    out_nodes[63 + u] = p;
    const float p7a = p * x6;          // node 127+2u
    const float p7b = p * (1.0f - x6); // node 128+2u

    // ---- depth 7 nodes ----
    out_nodes[127 + 2 * u] = p7a;
    out_nodes[128 + 2 * u] = p7b;

    // ---- leaves 4u..4u+3 (aligned float4 store) ----
    float4 leaf;
    leaf.x = p7a * x7a;
    leaf.y = p7a * (1.0f - x7a);
    leaf.z = p7b * x7b;
    leaf.w = p7b * (1.0f - x7b);
    *reinterpret_cast<float4*>(out + (size_t)b * 256 + 4 * u) = leaf;
}

extern "C" void kernel_launch(void* const* d_in, const int* in_sizes, int n_in,
                              void* d_out, int out_size) {
    const float* x = (const float*)d_in[0];  // (BATCH, 255) float32
    float* out = (float*)d_out;
    const int batch = in_sizes[0] / 255;     // 512
    tree_path_kernel<<<(batch / ROWS_PER_BLOCK), 256>>>(x, out, batch);
}

// round 5
// speedup vs baseline: 1.5306x; 1.5306x over previous
#include <cuda_runtime.h>

// Soft decision tree path probabilities — barrier-free, smem-free.
// DEPTH=8, N_NODES=255, N_LEAVES=256, BATCH=512.
//
// One row per 64-thread CTA (grid=512). Thread u owns the depth-6 subtree
// over leaves 4u..4u+3. Its 9 x-loads are index-computable, issued together:
//   top path  d=0..5 : node = (2^d-1) + (u >> (6-d))
//   depth-6          : 63 + u
//   depth-7          : 127+2u, 128+2u
// Running prefix product before the depth-d factor IS node_d's path prob:
// top nodes written by the leftmost thread of each subtree; nodes 63+u,
// 127+2u, 128+2u written unconditionally by their owner.
// Child 2i+1 takes factor x[i], child 2i+2 takes 1-x[i].
//
// Output: [ leaf_probs (512 x 256) ; node_probs (512 x 255) ] row-major.

__global__ __launch_bounds__(64) void tree_path_kernel(
    const float* __restrict__ x,   // (BATCH, 255)
    float* __restrict__ out,
    int batch)
{
    const unsigned u = threadIdx.x;          // 0..63
    const unsigned b = blockIdx.x;

    const float* __restrict__ xr = x + b * 255u;
    float* __restrict__ on = out + (unsigned)batch * 256u + b * 255u;

    // ---- issue all 9 independent loads up front ----
    float xt[6];
#pragma unroll
    for (int d = 0; d < 6; ++d) {
        const unsigned node = ((1u << d) - 1u) + (u >> (6 - d));
        xt[d] = __ldg(xr + node);
    }
    const float x6  = __ldg(xr + 63u + u);
    const float x7a = __ldg(xr + 127u + 2u * u);
    const float x7b = __ldg(xr + 128u + 2u * u);

    // ---- top path prefix product, emitting top node probs ----
    float p = 1.0f;
#pragma unroll
    for (int d = 0; d < 6; ++d) {
        const unsigned node = ((1u << d) - 1u) + (u >> (6 - d));
        if ((u & ((1u << (6 - d)) - 1u)) == 0u) {
            on[node] = p;                    // path prob of node at depth d
        }
        p *= ((u >> (5 - d)) & 1u) ? (1.0f - xt[d]) : xt[d];
    }

    // ---- exclusively-owned nodes ----
    on[63u + u] = p;                         // depth 6
    const float p7a = p * x6;                // node 127+2u
    const float p7b = p * (1.0f - x6);       // node 128+2u
    on[127u + 2u * u] = p7a;
    on[128u + 2u * u] = p7b;

    // ---- leaves 4u..4u+3 (aligned float4 store) ----
    float4 leaf;
    leaf.x = p7a * x7a;
    leaf.y = p7a * (1.0f - x7a);
    leaf.z = p7b * x7b;
    leaf.w = p7b * (1.0f - x7b);
    *reinterpret_cast<float4*>(out + b * 256u + 4u * u) = leaf;
}

extern "C" void kernel_launch(void* const* d_in, const int* in_sizes, int n_in,
                              void* d_out, int out_size) {
    const float* x = (const float*)d_in[0];  // (BATCH, 255) float32
    float* out = (float*)d_out;
    const int batch = in_sizes[0] / 255;     // 512
    tree_path_kernel<<<batch, 64>>>(x, out, batch);
}